// round 14
// baseline (speedup 1.0000x reference)
#include <cuda_runtime.h>
#include <cuda_fp16.h>
#include <cstdint>
#include <cstddef>

#define NROWS 8192
#define FDIM  128
#define BATCH 8

// Scratch (allocation-free rule: __device__ globals)
__device__ __half g_adj_h[(size_t)NROWS * NROWS];     // 128 MB fp16 adj
__device__ __half g_P[(size_t)BATCH * NROWS * FDIM];  // 16 MB  P = x@W

extern __shared__ __align__(1024) unsigned char dsm[];

// ---------------- helpers ----------------
__device__ __forceinline__ uint32_t smem_u32(const void* p){
  return (uint32_t)__cvta_generic_to_shared(p);
}
__device__ __forceinline__ void cp16(uint32_t dst, const void* src){
  asm volatile("cp.async.cg.shared.global [%0], [%1], 16;\n" :: "r"(dst), "l"(src));
}
__device__ __forceinline__ void cp_commit(){ asm volatile("cp.async.commit_group;\n" ::: "memory"); }
template<int N> __device__ __forceinline__ void cp_wait(){
  asm volatile("cp.async.wait_group %0;\n" :: "n"(N) : "memory");
}
__device__ __forceinline__ void ldsm4(uint32_t* r, uint32_t addr){
  asm volatile("ldmatrix.sync.aligned.m8n8.x4.shared.b16 {%0,%1,%2,%3}, [%4];\n"
    : "=r"(r[0]),"=r"(r[1]),"=r"(r[2]),"=r"(r[3]) : "r"(addr));
}
__device__ __forceinline__ void ldsm4t(uint32_t* r, uint32_t addr){
  asm volatile("ldmatrix.sync.aligned.m8n8.x4.trans.shared.b16 {%0,%1,%2,%3}, [%4];\n"
    : "=r"(r[0]),"=r"(r[1]),"=r"(r[2]),"=r"(r[3]) : "r"(addr));
}
__device__ __forceinline__ void mma16816(float* c, const uint32_t* a, const uint32_t* b){
  asm volatile("mma.sync.aligned.m16n8k16.row.col.f32.f16.f16.f32 "
    "{%0,%1,%2,%3}, {%4,%5,%6,%7}, {%8,%9}, {%0,%1,%2,%3};\n"
    : "+f"(c[0]),"+f"(c[1]),"+f"(c[2]),"+f"(c[3])
    : "r"(a[0]),"r"(a[1]),"r"(a[2]),"r"(a[3]), "r"(b[0]),"r"(b[1]));
}

// ---------------- K_prep: fused [P = x@W] + [adj fp32->fp16 convert] ----------------
// Blocks [0,512): one 128-row x@W tile each (scheduled FIRST to overlap convert).
// Blocks [512,2560): grid-stride convert of adj with streaming cache hints.
#define K1_SA 136
#define K1_SMEM (2 * 128 * K1_SA * 2)   // 69632 B

__global__ __launch_bounds__(256,1) void k_prep(const float* __restrict__ adj,
                                                const float* __restrict__ x,
                                                const float* __restrict__ w){
  if (blockIdx.x >= 512){
    // ---- adj convert (2048 blocks), streaming: don't thrash L2 ----
    size_t i = (size_t)(blockIdx.x - 512) * 256 + threadIdx.x;
    const size_t stride = (size_t)2048 * 256;
    const size_t n4 = (size_t)NROWS * NROWS / 4;
    const float4* src = (const float4*)adj;
    uint2* dst = (uint2*)g_adj_h;
    for (size_t j = i; j < n4; j += stride){
      float4 v = __ldcs(src + j);
      __half2 h0 = __floats2half2_rn(v.x, v.y);
      __half2 h1 = __floats2half2_rn(v.z, v.w);
      uint2 o;
      o.x = *reinterpret_cast<uint32_t*>(&h0);
      o.y = *reinterpret_cast<uint32_t*>(&h1);
      __stcs(dst + j, o);
    }
    return;
  }

  // ---- x@W tile (512 blocks) ----
  __half* As = (__half*)dsm;              // [128][K1_SA]
  __half* Bs = (__half*)dsm + 128*K1_SA;  // [128][K1_SA]
  const int bid2 = blockIdx.x;            // 0..511
  const int b  = bid2 >> 6;
  const int m0 = (bid2 & 63) * 128;
  const int tid = threadIdx.x;

  const float4* xs = (const float4*)(x + ((size_t)b*NROWS + m0)*FDIM);
  const float4* ws = (const float4*)w;
  #pragma unroll
  for (int i = 0; i < 16; i++){
    int seg = tid + i*256;
    int r = seg >> 5;
    int f = (seg & 31) * 4;
    float4 v = xs[(size_t)r*32 + (seg & 31)];
    __half2 h0 = __floats2half2_rn(v.x, v.y);
    __half2 h1 = __floats2half2_rn(v.z, v.w);
    uint2 u; u.x = *reinterpret_cast<uint32_t*>(&h0); u.y = *reinterpret_cast<uint32_t*>(&h1);
    *(uint2*)&As[r*K1_SA + f] = u;
    float4 vw = ws[seg];
    __half2 w0 = __floats2half2_rn(vw.x, vw.y);
    __half2 w1 = __floats2half2_rn(vw.z, vw.w);
    uint2 uw; uw.x = *reinterpret_cast<uint32_t*>(&w0); uw.y = *reinterpret_cast<uint32_t*>(&w1);
    *(uint2*)&Bs[r*K1_SA + f] = uw;
  }
  __syncthreads();

  const int lane = tid & 31, wid = tid >> 5;
  const int wm = wid >> 1, wn = wid & 1;        // 4 x 2 warps, 32x64 tiles
  float acc[2][8][4] = {};
  uint32_t as_u = smem_u32(As), bs_u = smem_u32(Bs);

  #pragma unroll
  for (int kk = 0; kk < 8; kk++){
    int k = kk * 16;
    uint32_t a[2][4], bflat[16];
    #pragma unroll
    for (int mi = 0; mi < 2; mi++){
      int r = wm*32 + mi*16 + (lane & 15);
      ldsm4(a[mi], as_u + (uint32_t)(r*K1_SA + k + ((lane>>4)<<3)) * 2);
    }
    #pragma unroll
    for (int g = 0; g < 4; g++){
      int rr = k + (lane & 15);
      int c  = wn*64 + g*16 + ((lane>>4)<<3);
      ldsm4t(&bflat[g*4], bs_u + (uint32_t)(rr*K1_SA + c) * 2);
    }
    #pragma unroll
    for (int mi = 0; mi < 2; mi++)
      #pragma unroll
      for (int ni = 0; ni < 8; ni++)
        mma16816(acc[mi][ni], a[mi], &bflat[ni*2]);
  }

  #pragma unroll
  for (int mi = 0; mi < 2; mi++){
    int r0 = m0 + wm*32 + mi*16 + (lane>>2);
    #pragma unroll
    for (int ni = 0; ni < 8; ni++){
      int c = wn*64 + ni*8 + (lane&3)*2;
      __half2 h0 = __floats2half2_rn(acc[mi][ni][0], acc[mi][ni][1]);
      __half2 h1 = __floats2half2_rn(acc[mi][ni][2], acc[mi][ni][3]);
      *(__half2*)&g_P[((size_t)b*NROWS + r0    )*FDIM + c] = h0;
      *(__half2*)&g_P[((size_t)b*NROWS + r0 + 8)*FDIM + c] = h1;
    }
  }
}

// ---------------- K2: out = normalize(adj@P + P + bias) ----------------
// BM=128, BN=128, BK=64; 256 threads = 8 warps as 4(m) x 2(n), 32x64 tiles.
// 3-stage cp.async pipeline, ONE __syncthreads per chunk. 2 CTAs/SM.
// Chunk body: kk0 fragments+MMAs issue BEFORE next-stage loads. (R11 exact.)
#define BM 128
#define BK 64
#define STAGES 3
#define SA2 72     // A smem row stride (halfs): 64 data + 8 pad
#define SB2 136    // B smem row stride (halfs): 128 data + 8 pad
#define A_STG (BM*SA2)             // 9216 halfs
#define B_STG (BK*SB2)             // 8704 halfs
#define K2_ABYTES (STAGES*A_STG*2)              // 55296
#define K2_BBYTES (STAGES*B_STG*2)              // 52224
#define K2_SMEM   (K2_ABYTES + K2_BBYTES + 2*BM*4)  // +snorm 1KB = 108544

__global__ __launch_bounds__(256,2) void k_main(const float* __restrict__ bias,
                                                float* __restrict__ out){
  __half* As    = (__half*)dsm;                           // [STAGES][BM][SA2]
  __half* Bs    = (__half*)(dsm + K2_ABYTES);             // [STAGES][BK][SB2]
  float*  snorm = (float*)(dsm + K2_ABYTES + K2_BBYTES);  // [2][BM]

  const int b  = blockIdx.x;
  const int m0 = blockIdx.y * BM;
  const int tid  = threadIdx.x;
  const int lane = tid & 31, wid = tid >> 5;
  const int wm = wid >> 1, wn = wid & 1;              // 4 x 2 warps, 32x64 tiles

  const __half* gA = g_adj_h + (size_t)m0 * NROWS;
  const __half* gB = g_P + (size_t)b * NROWS * FDIM;

  uint32_t as_u = smem_u32(As), bs_u = smem_u32(Bs);
  float acc[2][8][4] = {};

  // hoisted per-thread addressing: gmem element offsets + absolute smem dst bases
  uint32_t offA0, dA0, offB0, dB0;
  {
    int rA = tid >> 3, cA = (tid & 7) * 8;
    offA0 = (uint32_t)rA * NROWS + cA;
    dA0   = as_u + (uint32_t)(rA*SA2 + cA) * 2;
    int rB = tid >> 4, cB = (tid & 15) * 8;
    offB0 = (uint32_t)rB * FDIM + cB;
    dB0   = bs_u + (uint32_t)(rB*SB2 + cB) * 2;
  }

  auto loadc = [&](int ci){
    int st = ci % STAGES;
    uint32_t kcA = (uint32_t)ci * BK;
    uint32_t kcB = (uint32_t)ci * (BK*FDIM);
    uint32_t soA = (uint32_t)st * (A_STG*2);
    uint32_t soB = (uint32_t)st * (B_STG*2);
    #pragma unroll
    for (int i = 0; i < 4; i++)
      cp16(dA0 + soA + i*(32*SA2*2), gA + offA0 + kcA + i*(32*NROWS));
    #pragma unroll
    for (int i = 0; i < 4; i++)
      cp16(dB0 + soB + i*(16*SB2*2), gB + offB0 + kcB + i*(16*FDIM));
  };

  loadc(0); cp_commit();
  loadc(1); cp_commit();

  const int NCHUNK = NROWS / BK;   // 128
  for (int ci = 0; ci < NCHUNK; ci++){
    cp_wait<1>();
    __syncthreads();
    const int st = ci % STAGES;
    const uint32_t aBase = (uint32_t)(st*A_STG)*2;
    const uint32_t bBase = (uint32_t)(st*B_STG)*2;

    // ---- kk = 0 first: feed the tensor pipe before issuing new loads ----
    {
      uint32_t a[2][4], bflat[16];
      #pragma unroll
      for (int mi = 0; mi < 2; mi++){
        int r = wm*32 + mi*16 + (lane & 15);
        ldsm4(a[mi], as_u + aBase + (uint32_t)(r*SA2 + ((lane>>4)<<3)) * 2);
      }
      #pragma unroll
      for (int g = 0; g < 4; g++){
        int rr = (lane & 15);
        int c  = wn*64 + g*16 + ((lane>>4)<<3);
        ldsm4t(&bflat[g*4], bs_u + bBase + (uint32_t)(rr*SB2 + c) * 2);
      }
      #pragma unroll
      for (int mi = 0; mi < 2; mi++)
        #pragma unroll
        for (int ni = 0; ni < 8; ni++)
          mma16816(acc[mi][ni], a[mi], &bflat[ni*2]);
    }

    // ---- issue next-stage loads while kk0 MMAs drain ----
    if (ci + 2 < NCHUNK) loadc(ci + 2);
    cp_commit();   // empty group at tail keeps wait<1> honest

    // ---- kk = 1..3 ----
    #pragma unroll
    for (int kk = 1; kk < 4; kk++){
      int k = kk * 16;
      uint32_t a[2][4], bflat[16];
      #pragma unroll
      for (int mi = 0; mi < 2; mi++){
        int r = wm*32 + mi*16 + (lane & 15);
        ldsm4(a[mi], as_u + aBase + (uint32_t)(r*SA2 + k + ((lane>>4)<<3)) * 2);
      }
      #pragma unroll
      for (int g = 0; g < 4; g++){
        int rr = k + (lane & 15);
        int c  = wn*64 + g*16 + ((lane>>4)<<3);
        ldsm4t(&bflat[g*4], bs_u + bBase + (uint32_t)(rr*SB2 + c) * 2);
      }
      #pragma unroll
      for (int mi = 0; mi < 2; mi++)
        #pragma unroll
        for (int ni = 0; ni < 8; ni++)
          mma16816(acc[mi][ni], a[mi], &bflat[ni*2]);
    }
  }
  cp_wait<0>();

  // ---- epilogue: + P + bias, row L2 norm over 128 cols, scaled store ----
  float2 bias2[8];
  #pragma unroll
  for (int ni = 0; ni < 8; ni++){
    int c = wn*64 + ni*8 + (lane&3)*2;
    bias2[ni] = *(const float2*)(bias + c);
  }
  #pragma unroll
  for (int mi = 0; mi < 2; mi++){
    int r0 = m0 + wm*32 + mi*16 + (lane>>2);
    int r1 = r0 + 8;
    float ss0 = 0.f, ss1 = 0.f;
    #pragma unroll
    for (int ni = 0; ni < 8; ni++){
      int c = wn*64 + ni*8 + (lane&3)*2;
      __half2 p0 = *(const __half2*)(gB + (size_t)r0*FDIM + c);
      __half2 p1 = *(const __half2*)(gB + (size_t)r1*FDIM + c);
      float v0 = acc[mi][ni][0] + __low2float(p0)  + bias2[ni].x;
      float v1 = acc[mi][ni][1] + __high2float(p0) + bias2[ni].y;
      float v2 = acc[mi][ni][2] + __low2float(p1)  + bias2[ni].x;
      float v3 = acc[mi][ni][3] + __high2float(p1) + bias2[ni].y;
      acc[mi][ni][0] = v0; acc[mi][ni][1] = v1;
      acc[mi][ni][2] = v2; acc[mi][ni][3] = v3;
      ss0 += v0*v0 + v1*v1;
      ss1 += v2*v2 + v3*v3;
    }
    ss0 += __shfl_xor_sync(0xffffffffu, ss0, 1);
    ss0 += __shfl_xor_sync(0xffffffffu, ss0, 2);
    ss1 += __shfl_xor_sync(0xffffffffu, ss1, 1);
    ss1 += __shfl_xor_sync(0xffffffffu, ss1, 2);
    if ((lane & 3) == 0){
      snorm[wn*BM + (r0 - m0)] = ss0;
      snorm[wn*BM + (r1 - m0)] = ss1;
    }
  }
  __syncthreads();
  #pragma unroll
  for (int mi = 0; mi < 2; mi++){
    int r0 = m0 + wm*32 + mi*16 + (lane>>2);
    int r1 = r0 + 8;
    float t0 = snorm[r0 - m0] + snorm[BM + r0 - m0];
    float t1 = snorm[r1 - m0] + snorm[BM + r1 - m0];
    float inv0 = 1.0f / fmaxf(sqrtf(t0), 1e-12f);
    float inv1 = 1.0f / fmaxf(sqrtf(t1), 1e-12f);
    #pragma unroll
    for (int ni = 0; ni < 8; ni++){
      int c = wn*64 + ni*8 + (lane&3)*2;
      float2 o0 = make_float2(acc[mi][ni][0]*inv0, acc[mi][ni][1]*inv0);
      float2 o1 = make_float2(acc[mi][ni][2]*inv1, acc[mi][ni][3]*inv1);
      *(float2*)(out + ((size_t)b*NROWS + r0)*FDIM + c) = o0;
      *(float2*)(out + ((size_t)b*NROWS + r1)*FDIM + c) = o1;
    }
  }
}

// ---------------- launch ----------------
extern "C" void kernel_launch(void* const* d_in, const int* in_sizes, int n_in,
                              void* d_out, int out_size){
  (void)in_sizes; (void)n_in; (void)out_size;
  const float* x    = (const float*)d_in[0];
  const float* adj  = (const float*)d_in[1];
  const float* w    = (const float*)d_in[2];
  const float* bias = (const float*)d_in[3];
  float* out = (float*)d_out;

  cudaFuncSetAttribute(k_prep, cudaFuncAttributeMaxDynamicSharedMemorySize, K1_SMEM);
  cudaFuncSetAttribute(k_main, cudaFuncAttributeMaxDynamicSharedMemorySize, K2_SMEM);

  k_prep<<<2560, 256, K1_SMEM>>>(adj, x, w);
  k_main<<<dim3(BATCH, NROWS/BM), 256, K2_SMEM>>>(bias, out);
}

// round 15
// speedup vs baseline: 1.8645x; 1.8645x over previous
#include <cuda_runtime.h>
#include <cuda_fp16.h>
#include <cstdint>
#include <cstddef>

#define NROWS 8192
#define FDIM  128
#define BATCH 8

// Scratch (allocation-free rule: __device__ globals)
__device__ __half g_adj_h[(size_t)NROWS * NROWS];     // 128 MB fp16 adj
__device__ __half g_P[(size_t)BATCH * NROWS * FDIM];  // 16 MB  P = x@W

extern __shared__ __align__(1024) unsigned char dsm[];

// ---------------- helpers ----------------
__device__ __forceinline__ uint32_t smem_u32(const void* p){
  return (uint32_t)__cvta_generic_to_shared(p);
}
__device__ __forceinline__ void cp16(uint32_t dst, const void* src){
  asm volatile("cp.async.cg.shared.global [%0], [%1], 16;\n" :: "r"(dst), "l"(src));
}
__device__ __forceinline__ void cp_commit(){ asm volatile("cp.async.commit_group;\n" ::: "memory"); }
template<int N> __device__ __forceinline__ void cp_wait(){
  asm volatile("cp.async.wait_group %0;\n" :: "n"(N) : "memory");
}
__device__ __forceinline__ void ldsm4(uint32_t* r, uint32_t addr){
  asm volatile("ldmatrix.sync.aligned.m8n8.x4.shared.b16 {%0,%1,%2,%3}, [%4];\n"
    : "=r"(r[0]),"=r"(r[1]),"=r"(r[2]),"=r"(r[3]) : "r"(addr));
}
__device__ __forceinline__ void ldsm4t(uint32_t* r, uint32_t addr){
  asm volatile("ldmatrix.sync.aligned.m8n8.x4.trans.shared.b16 {%0,%1,%2,%3}, [%4];\n"
    : "=r"(r[0]),"=r"(r[1]),"=r"(r[2]),"=r"(r[3]) : "r"(addr));
}
__device__ __forceinline__ void mma16816(float* c, const uint32_t* a, const uint32_t* b){
  asm volatile("mma.sync.aligned.m16n8k16.row.col.f32.f16.f16.f32 "
    "{%0,%1,%2,%3}, {%4,%5,%6,%7}, {%8,%9}, {%0,%1,%2,%3};\n"
    : "+f"(c[0]),"+f"(c[1]),"+f"(c[2]),"+f"(c[3])
    : "r"(a[0]),"r"(a[1]),"r"(a[2]),"r"(a[3]), "r"(b[0]),"r"(b[1]));
}

// ---------------- K_prep: fused [P = x@W] + [adj fp32->fp16 convert] ----------------
// Blocks [0,512): one 128-row x@W tile each (scheduled FIRST to overlap convert).
// Blocks [512,2560): grid-stride convert of adj (plain loads/stores — .cs hints
// measured 3x slower on this part, do not reintroduce).
#define K1_SA 136
#define K1_SMEM (2 * 128 * K1_SA * 2)   // 69632 B

__global__ __launch_bounds__(256,1) void k_prep(const float* __restrict__ adj,
                                                const float* __restrict__ x,
                                                const float* __restrict__ w){
  if (blockIdx.x >= 512){
    // ---- adj convert (2048 blocks) ----
    size_t i = (size_t)(blockIdx.x - 512) * 256 + threadIdx.x;
    const size_t stride = (size_t)2048 * 256;
    const size_t n4 = (size_t)NROWS * NROWS / 4;
    const float4* src = (const float4*)adj;
    uint2* dst = (uint2*)g_adj_h;
    for (size_t j = i; j < n4; j += stride){
      float4 v = src[j];
      __half2 h0 = __floats2half2_rn(v.x, v.y);
      __half2 h1 = __floats2half2_rn(v.z, v.w);
      uint2 o;
      o.x = *reinterpret_cast<uint32_t*>(&h0);
      o.y = *reinterpret_cast<uint32_t*>(&h1);
      dst[j] = o;
    }
    return;
  }

  // ---- x@W tile (512 blocks) ----
  __half* As = (__half*)dsm;              // [128][K1_SA]
  __half* Bs = (__half*)dsm + 128*K1_SA;  // [128][K1_SA]
  const int bid2 = blockIdx.x;            // 0..511
  const int b  = bid2 >> 6;
  const int m0 = (bid2 & 63) * 128;
  const int tid = threadIdx.x;

  const float4* xs = (const float4*)(x + ((size_t)b*NROWS + m0)*FDIM);
  const float4* ws = (const float4*)w;
  #pragma unroll
  for (int i = 0; i < 16; i++){
    int seg = tid + i*256;
    int r = seg >> 5;
    int f = (seg & 31) * 4;
    float4 v = xs[(size_t)r*32 + (seg & 31)];
    __half2 h0 = __floats2half2_rn(v.x, v.y);
    __half2 h1 = __floats2half2_rn(v.z, v.w);
    uint2 u; u.x = *reinterpret_cast<uint32_t*>(&h0); u.y = *reinterpret_cast<uint32_t*>(&h1);
    *(uint2*)&As[r*K1_SA + f] = u;
    float4 vw = ws[seg];
    __half2 w0 = __floats2half2_rn(vw.x, vw.y);
    __half2 w1 = __floats2half2_rn(vw.z, vw.w);
    uint2 uw; uw.x = *reinterpret_cast<uint32_t*>(&w0); uw.y = *reinterpret_cast<uint32_t*>(&w1);
    *(uint2*)&Bs[r*K1_SA + f] = uw;
  }
  __syncthreads();

  const int lane = tid & 31, wid = tid >> 5;
  const int wm = wid >> 1, wn = wid & 1;        // 4 x 2 warps, 32x64 tiles
  float acc[2][8][4] = {};
  uint32_t as_u = smem_u32(As), bs_u = smem_u32(Bs);

  #pragma unroll
  for (int kk = 0; kk < 8; kk++){
    int k = kk * 16;
    uint32_t a[2][4], bflat[16];
    #pragma unroll
    for (int mi = 0; mi < 2; mi++){
      int r = wm*32 + mi*16 + (lane & 15);
      ldsm4(a[mi], as_u + (uint32_t)(r*K1_SA + k + ((lane>>4)<<3)) * 2);
    }
    #pragma unroll
    for (int g = 0; g < 4; g++){
      int rr = k + (lane & 15);
      int c  = wn*64 + g*16 + ((lane>>4)<<3);
      ldsm4t(&bflat[g*4], bs_u + (uint32_t)(rr*K1_SA + c) * 2);
    }
    #pragma unroll
    for (int mi = 0; mi < 2; mi++)
      #pragma unroll
      for (int ni = 0; ni < 8; ni++)
        mma16816(acc[mi][ni], a[mi], &bflat[ni*2]);
  }

  #pragma unroll
  for (int mi = 0; mi < 2; mi++){
    int r0 = m0 + wm*32 + mi*16 + (lane>>2);
    #pragma unroll
    for (int ni = 0; ni < 8; ni++){
      int c = wn*64 + ni*8 + (lane&3)*2;
      __half2 h0 = __floats2half2_rn(acc[mi][ni][0], acc[mi][ni][1]);
      __half2 h1 = __floats2half2_rn(acc[mi][ni][2], acc[mi][ni][3]);
      *(__half2*)&g_P[((size_t)b*NROWS + r0    )*FDIM + c] = h0;
      *(__half2*)&g_P[((size_t)b*NROWS + r0 + 8)*FDIM + c] = h1;
    }
  }
}

// ---------------- K2: out = normalize(adj@P + P + bias) ----------------
// BM=128, BN=128, BK=64; 256 threads = 8 warps as 4(m) x 2(n), 32x64 tiles.
// 3-stage cp.async pipeline, ONE __syncthreads per chunk. 2 CTAs/SM.
// Chunk body: kk0 fragments+MMAs issue BEFORE next-stage loads. (R11 exact.)
#define BM 128
#define BK 64
#define STAGES 3
#define SA2 72     // A smem row stride (halfs): 64 data + 8 pad
#define SB2 136    // B smem row stride (halfs): 128 data + 8 pad
#define A_STG (BM*SA2)             // 9216 halfs
#define B_STG (BK*SB2)             // 8704 halfs
#define K2_ABYTES (STAGES*A_STG*2)              // 55296
#define K2_BBYTES (STAGES*B_STG*2)              // 52224
#define K2_SMEM   (K2_ABYTES + K2_BBYTES + 2*BM*4)  // +snorm 1KB = 108544

__global__ __launch_bounds__(256,2) void k_main(const float* __restrict__ bias,
                                                float* __restrict__ out){
  __half* As    = (__half*)dsm;                           // [STAGES][BM][SA2]
  __half* Bs    = (__half*)(dsm + K2_ABYTES);             // [STAGES][BK][SB2]
  float*  snorm = (float*)(dsm + K2_ABYTES + K2_BBYTES);  // [2][BM]

  const int b  = blockIdx.x;
  const int m0 = blockIdx.y * BM;
  const int tid  = threadIdx.x;
  const int lane = tid & 31, wid = tid >> 5;
  const int wm = wid >> 1, wn = wid & 1;              // 4 x 2 warps, 32x64 tiles

  const __half* gA = g_adj_h + (size_t)m0 * NROWS;
  const __half* gB = g_P + (size_t)b * NROWS * FDIM;

  uint32_t as_u = smem_u32(As), bs_u = smem_u32(Bs);
  float acc[2][8][4] = {};

  // hoisted per-thread addressing: gmem element offsets + absolute smem dst bases
  uint32_t offA0, dA0, offB0, dB0;
  {
    int rA = tid >> 3, cA = (tid & 7) * 8;
    offA0 = (uint32_t)rA * NROWS + cA;
    dA0   = as_u + (uint32_t)(rA*SA2 + cA) * 2;
    int rB = tid >> 4, cB = (tid & 15) * 8;
    offB0 = (uint32_t)rB * FDIM + cB;
    dB0   = bs_u + (uint32_t)(rB*SB2 + cB) * 2;
  }

  auto loadc = [&](int ci){
    int st = ci % STAGES;
    uint32_t kcA = (uint32_t)ci * BK;
    uint32_t kcB = (uint32_t)ci * (BK*FDIM);
    uint32_t soA = (uint32_t)st * (A_STG*2);
    uint32_t soB = (uint32_t)st * (B_STG*2);
    #pragma unroll
    for (int i = 0; i < 4; i++)
      cp16(dA0 + soA + i*(32*SA2*2), gA + offA0 + kcA + i*(32*NROWS));
    #pragma unroll
    for (int i = 0; i < 4; i++)
      cp16(dB0 + soB + i*(16*SB2*2), gB + offB0 + kcB + i*(16*FDIM));
  };

  loadc(0); cp_commit();
  loadc(1); cp_commit();

  const int NCHUNK = NROWS / BK;   // 128
  for (int ci = 0; ci < NCHUNK; ci++){
    cp_wait<1>();
    __syncthreads();
    const int st = ci % STAGES;
    const uint32_t aBase = (uint32_t)(st*A_STG)*2;
    const uint32_t bBase = (uint32_t)(st*B_STG)*2;

    // ---- kk = 0 first: feed the tensor pipe before issuing new loads ----
    {
      uint32_t a[2][4], bflat[16];
      #pragma unroll
      for (int mi = 0; mi < 2; mi++){
        int r = wm*32 + mi*16 + (lane & 15);
        ldsm4(a[mi], as_u + aBase + (uint32_t)(r*SA2 + ((lane>>4)<<3)) * 2);
      }
      #pragma unroll
      for (int g = 0; g < 4; g++){
        int rr = (lane & 15);
        int c  = wn*64 + g*16 + ((lane>>4)<<3);
        ldsm4t(&bflat[g*4], bs_u + bBase + (uint32_t)(rr*SB2 + c) * 2);
      }
      #pragma unroll
      for (int mi = 0; mi < 2; mi++)
        #pragma unroll
        for (int ni = 0; ni < 8; ni++)
          mma16816(acc[mi][ni], a[mi], &bflat[ni*2]);
    }

    // ---- issue next-stage loads while kk0 MMAs drain ----
    if (ci + 2 < NCHUNK) loadc(ci + 2);
    cp_commit();   // empty group at tail keeps wait<1> honest

    // ---- kk = 1..3 ----
    #pragma unroll
    for (int kk = 1; kk < 4; kk++){
      int k = kk * 16;
      uint32_t a[2][4], bflat[16];
      #pragma unroll
      for (int mi = 0; mi < 2; mi++){
        int r = wm*32 + mi*16 + (lane & 15);
        ldsm4(a[mi], as_u + aBase + (uint32_t)(r*SA2 + k + ((lane>>4)<<3)) * 2);
      }
      #pragma unroll
      for (int g = 0; g < 4; g++){
        int rr = k + (lane & 15);
        int c  = wn*64 + g*16 + ((lane>>4)<<3);
        ldsm4t(&bflat[g*4], bs_u + bBase + (uint32_t)(rr*SB2 + c) * 2);
      }
      #pragma unroll
      for (int mi = 0; mi < 2; mi++)
        #pragma unroll
        for (int ni = 0; ni < 8; ni++)
          mma16816(acc[mi][ni], a[mi], &bflat[ni*2]);
    }
  }
  cp_wait<0>();

  // ---- epilogue: + P + bias, row L2 norm over 128 cols, scaled store ----
  float2 bias2[8];
  #pragma unroll
  for (int ni = 0; ni < 8; ni++){
    int c = wn*64 + ni*8 + (lane&3)*2;
    bias2[ni] = *(const float2*)(bias + c);
  }
  #pragma unroll
  for (int mi = 0; mi < 2; mi++){
    int r0 = m0 + wm*32 + mi*16 + (lane>>2);
    int r1 = r0 + 8;
    float ss0 = 0.f, ss1 = 0.f;
    #pragma unroll
    for (int ni = 0; ni < 8; ni++){
      int c = wn*64 + ni*8 + (lane&3)*2;
      __half2 p0 = *(const __half2*)(gB + (size_t)r0*FDIM + c);
      __half2 p1 = *(const __half2*)(gB + (size_t)r1*FDIM + c);
      float v0 = acc[mi][ni][0] + __low2float(p0)  + bias2[ni].x;
      float v1 = acc[mi][ni][1] + __high2float(p0) + bias2[ni].y;
      float v2 = acc[mi][ni][2] + __low2float(p1)  + bias2[ni].x;
      float v3 = acc[mi][ni][3] + __high2float(p1) + bias2[ni].y;
      acc[mi][ni][0] = v0; acc[mi][ni][1] = v1;
      acc[mi][ni][2] = v2; acc[mi][ni][3] = v3;
      ss0 += v0*v0 + v1*v1;
      ss1 += v2*v2 + v3*v3;
    }
    ss0 += __shfl_xor_sync(0xffffffffu, ss0, 1);
    ss0 += __shfl_xor_sync(0xffffffffu, ss0, 2);
    ss1 += __shfl_xor_sync(0xffffffffu, ss1, 1);
    ss1 += __shfl_xor_sync(0xffffffffu, ss1, 2);
    if ((lane & 3) == 0){
      snorm[wn*BM + (r0 - m0)] = ss0;
      snorm[wn*BM + (r1 - m0)] = ss1;
    }
  }
  __syncthreads();
  #pragma unroll
  for (int mi = 0; mi < 2; mi++){
    int r0 = m0 + wm*32 + mi*16 + (lane>>2);
    int r1 = r0 + 8;
    float t0 = snorm[r0 - m0] + snorm[BM + r0 - m0];
    float t1 = snorm[r1 - m0] + snorm[BM + r1 - m0];
    float inv0 = 1.0f / fmaxf(sqrtf(t0), 1e-12f);
    float inv1 = 1.0f / fmaxf(sqrtf(t1), 1e-12f);
    #pragma unroll
    for (int ni = 0; ni < 8; ni++){
      int c = wn*64 + ni*8 + (lane&3)*2;
      float2 o0 = make_float2(acc[mi][ni][0]*inv0, acc[mi][ni][1]*inv0);
      float2 o1 = make_float2(acc[mi][ni][2]*inv1, acc[mi][ni][3]*inv1);
      *(float2*)(out + ((size_t)b*NROWS + r0)*FDIM + c) = o0;
      *(float2*)(out + ((size_t)b*NROWS + r1)*FDIM + c) = o1;
    }
  }
}

// ---------------- launch ----------------
extern "C" void kernel_launch(void* const* d_in, const int* in_sizes, int n_in,
                              void* d_out, int out_size){
  (void)in_sizes; (void)n_in; (void)out_size;
  const float* x    = (const float*)d_in[0];
  const float* adj  = (const float*)d_in[1];
  const float* w    = (const float*)d_in[2];
  const float* bias = (const float*)d_in[3];
  float* out = (float*)d_out;

  cudaFuncSetAttribute(k_prep, cudaFuncAttributeMaxDynamicSharedMemorySize, K1_SMEM);
  cudaFuncSetAttribute(k_main, cudaFuncAttributeMaxDynamicSharedMemorySize, K2_SMEM);

  k_prep<<<2560, 256, K1_SMEM>>>(adj, x, w);
  k_main<<<dim3(BATCH, NROWS/BM), 256, K2_SMEM>>>(bias, out);
}

// round 16
// speedup vs baseline: 1.8708x; 1.0034x over previous
#include <cuda_runtime.h>
#include <cuda_fp16.h>
#include <cstdint>
#include <cstddef>

#define NROWS 8192
#define FDIM  128
#define BATCH 8

// Scratch (allocation-free rule: __device__ globals)
__device__ __half g_adj_h[(size_t)NROWS * NROWS];     // 128 MB fp16 adj
__device__ __half g_P[(size_t)BATCH * NROWS * FDIM];  // 16 MB  P = x@W
__device__ unsigned g_flag[64];                       // per row-block convert counters

extern __shared__ __align__(1024) unsigned char dsm[];

// ---------------- helpers ----------------
__device__ __forceinline__ uint32_t smem_u32(const void* p){
  return (uint32_t)__cvta_generic_to_shared(p);
}
__device__ __forceinline__ void cp16(uint32_t dst, const void* src){
  asm volatile("cp.async.cg.shared.global [%0], [%1], 16;\n" :: "r"(dst), "l"(src));
}
__device__ __forceinline__ void cp_commit(){ asm volatile("cp.async.commit_group;\n" ::: "memory"); }
template<int N> __device__ __forceinline__ void cp_wait(){
  asm volatile("cp.async.wait_group %0;\n" :: "n"(N) : "memory");
}
__device__ __forceinline__ void ldsm4(uint32_t* r, uint32_t addr){
  asm volatile("ldmatrix.sync.aligned.m8n8.x4.shared.b16 {%0,%1,%2,%3}, [%4];\n"
    : "=r"(r[0]),"=r"(r[1]),"=r"(r[2]),"=r"(r[3]) : "r"(addr));
}
__device__ __forceinline__ void ldsm4t(uint32_t* r, uint32_t addr){
  asm volatile("ldmatrix.sync.aligned.m8n8.x4.trans.shared.b16 {%0,%1,%2,%3}, [%4];\n"
    : "=r"(r[0]),"=r"(r[1]),"=r"(r[2]),"=r"(r[3]) : "r"(addr));
}
__device__ __forceinline__ void mma16816(float* c, const uint32_t* a, const uint32_t* b){
  asm volatile("mma.sync.aligned.m16n8k16.row.col.f32.f16.f16.f32 "
    "{%0,%1,%2,%3}, {%4,%5,%6,%7}, {%8,%9}, {%0,%1,%2,%3};\n"
    : "+f"(c[0]),"+f"(c[1]),"+f"(c[2]),"+f"(c[3])
    : "r"(a[0]),"r"(a[1]),"r"(a[2]),"r"(a[3]), "r"(b[0]),"r"(b[1]));
}

// ---------------- K_prep: P = x @ W only (+ flag reset) ----------------
#define K1_SA 136
#define K1_SMEM (2 * 128 * K1_SA * 2)   // 69632 B

__global__ __launch_bounds__(256,1) void k_prep(const float* __restrict__ x,
                                                const float* __restrict__ w){
  const int tid = threadIdx.x;
  if (blockIdx.x == 0 && tid < 64) g_flag[tid] = 0u;

  __half* As = (__half*)dsm;              // [128][K1_SA]
  __half* Bs = (__half*)dsm + 128*K1_SA;  // [128][K1_SA]
  const int bid2 = blockIdx.x;            // 0..511
  const int b  = bid2 >> 6;
  const int m0 = (bid2 & 63) * 128;

  const float4* xs = (const float4*)(x + ((size_t)b*NROWS + m0)*FDIM);
  const float4* ws = (const float4*)w;
  #pragma unroll
  for (int i = 0; i < 16; i++){
    int seg = tid + i*256;
    int r = seg >> 5;
    int f = (seg & 31) * 4;
    float4 v = xs[(size_t)r*32 + (seg & 31)];
    __half2 h0 = __floats2half2_rn(v.x, v.y);
    __half2 h1 = __floats2half2_rn(v.z, v.w);
    uint2 u; u.x = *reinterpret_cast<uint32_t*>(&h0); u.y = *reinterpret_cast<uint32_t*>(&h1);
    *(uint2*)&As[r*K1_SA + f] = u;
    float4 vw = ws[seg];
    __half2 w0 = __floats2half2_rn(vw.x, vw.y);
    __half2 w1 = __floats2half2_rn(vw.z, vw.w);
    uint2 uw; uw.x = *reinterpret_cast<uint32_t*>(&w0); uw.y = *reinterpret_cast<uint32_t*>(&w1);
    *(uint2*)&Bs[r*K1_SA + f] = uw;
  }
  __syncthreads();

  const int lane = tid & 31, wid = tid >> 5;
  const int wm = wid >> 1, wn = wid & 1;        // 4 x 2 warps, 32x64 tiles
  float acc[2][8][4] = {};
  uint32_t as_u = smem_u32(As), bs_u = smem_u32(Bs);

  #pragma unroll
  for (int kk = 0; kk < 8; kk++){
    int k = kk * 16;
    uint32_t a[2][4], bflat[16];
    #pragma unroll
    for (int mi = 0; mi < 2; mi++){
      int r = wm*32 + mi*16 + (lane & 15);
      ldsm4(a[mi], as_u + (uint32_t)(r*K1_SA + k + ((lane>>4)<<3)) * 2);
    }
    #pragma unroll
    for (int g = 0; g < 4; g++){
      int rr = k + (lane & 15);
      int c  = wn*64 + g*16 + ((lane>>4)<<3);
      ldsm4t(&bflat[g*4], bs_u + (uint32_t)(rr*K1_SA + c) * 2);
    }
    #pragma unroll
    for (int mi = 0; mi < 2; mi++)
      #pragma unroll
      for (int ni = 0; ni < 8; ni++)
        mma16816(acc[mi][ni], a[mi], &bflat[ni*2]);
  }

  #pragma unroll
  for (int mi = 0; mi < 2; mi++){
    int r0 = m0 + wm*32 + mi*16 + (lane>>2);
    #pragma unroll
    for (int ni = 0; ni < 8; ni++){
      int c = wn*64 + ni*8 + (lane&3)*2;
      __half2 h0 = __floats2half2_rn(acc[mi][ni][0], acc[mi][ni][1]);
      __half2 h1 = __floats2half2_rn(acc[mi][ni][2], acc[mi][ni][3]);
      *(__half2*)&g_P[((size_t)b*NROWS + r0    )*FDIM + c] = h0;
      *(__half2*)&g_P[((size_t)b*NROWS + r0 + 8)*FDIM + c] = h1;
    }
  }
}

// ---------------- K2: self-converting fused GEMM + epilogue ----------------
// Each CTA (b,y) first converts 16 rows of adj (fp32->fp16) for row-block y,
// then rendezvouses with its 7 sibling CTAs (flag[y]==8), then runs the
// proven BM=128/BK=64/3-stage/1-sync mainloop (R11/R15 exact).
#define BM 128
#define BK 64
#define STAGES 3
#define SA2 72     // A smem row stride (halfs): 64 data + 8 pad
#define SB2 136    // B smem row stride (halfs): 128 data + 8 pad
#define A_STG (BM*SA2)             // 9216 halfs
#define B_STG (BK*SB2)             // 8704 halfs
#define K2_ABYTES (STAGES*A_STG*2)              // 55296
#define K2_BBYTES (STAGES*B_STG*2)              // 52224
#define K2_SMEM   (K2_ABYTES + K2_BBYTES + 2*BM*4)  // +snorm 1KB = 108544

__global__ __launch_bounds__(256,2) void k_main(const float* __restrict__ adj,
                                                const float* __restrict__ bias,
                                                float* __restrict__ out){
  __half* As    = (__half*)dsm;                           // [STAGES][BM][SA2]
  __half* Bs    = (__half*)(dsm + K2_ABYTES);             // [STAGES][BK][SB2]
  float*  snorm = (float*)(dsm + K2_ABYTES + K2_BBYTES);  // [2][BM]

  const int b  = blockIdx.x;
  const int y  = blockIdx.y;
  const int m0 = y * BM;
  const int tid  = threadIdx.x;
  const int lane = tid & 31, wid = tid >> 5;
  const int wm = wid >> 1, wn = wid & 1;              // 4 x 2 warps, 32x64 tiles

  // ---- phase 0: convert our 16 adj rows (m0 + b*16 .. +16) fp32 -> fp16 ----
  {
    const int r0 = m0 + b*16;
    const float4* src = (const float4*)(adj + (size_t)r0 * NROWS);
    uint2* dst = (uint2*)(g_adj_h + (size_t)r0 * NROWS);
    // 16 rows x 2048 float4 = 32768; 128 per thread
    #pragma unroll 4
    for (int i = 0; i < 128; i++){
      int idx = tid + i*256;
      float4 v = src[idx];
      __half2 h0 = __floats2half2_rn(v.x, v.y);
      __half2 h1 = __floats2half2_rn(v.z, v.w);
      uint2 o;
      o.x = *reinterpret_cast<uint32_t*>(&h0);
      o.y = *reinterpret_cast<uint32_t*>(&h1);
      dst[idx] = o;
    }
    __syncthreads();
    if (tid == 0){
      __threadfence();
      atomicAdd(&g_flag[y], 1u);
      while (atomicAdd(&g_flag[y], 0u) < 8u) { }
      __threadfence();
    }
    __syncthreads();
  }

  const __half* gA = g_adj_h + (size_t)m0 * NROWS;
  const __half* gB = g_P + (size_t)b * NROWS * FDIM;

  uint32_t as_u = smem_u32(As), bs_u = smem_u32(Bs);
  float acc[2][8][4] = {};

  // hoisted per-thread addressing: gmem element offsets + absolute smem dst bases
  uint32_t offA0, dA0, offB0, dB0;
  {
    int rA = tid >> 3, cA = (tid & 7) * 8;
    offA0 = (uint32_t)rA * NROWS + cA;
    dA0   = as_u + (uint32_t)(rA*SA2 + cA) * 2;
    int rB = tid >> 4, cB = (tid & 15) * 8;
    offB0 = (uint32_t)rB * FDIM + cB;
    dB0   = bs_u + (uint32_t)(rB*SB2 + cB) * 2;
  }

  auto loadc = [&](int ci){
    int st = ci % STAGES;
    uint32_t kcA = (uint32_t)ci * BK;
    uint32_t kcB = (uint32_t)ci * (BK*FDIM);
    uint32_t soA = (uint32_t)st * (A_STG*2);
    uint32_t soB = (uint32_t)st * (B_STG*2);
    #pragma unroll
    for (int i = 0; i < 4; i++)
      cp16(dA0 + soA + i*(32*SA2*2), gA + offA0 + kcA + i*(32*NROWS));
    #pragma unroll
    for (int i = 0; i < 4; i++)
      cp16(dB0 + soB + i*(16*SB2*2), gB + offB0 + kcB + i*(16*FDIM));
  };

  loadc(0); cp_commit();
  loadc(1); cp_commit();

  const int NCHUNK = NROWS / BK;   // 128
  for (int ci = 0; ci < NCHUNK; ci++){
    cp_wait<1>();
    __syncthreads();
    const int st = ci % STAGES;
    const uint32_t aBase = (uint32_t)(st*A_STG)*2;
    const uint32_t bBase = (uint32_t)(st*B_STG)*2;

    // ---- kk = 0 first: feed the tensor pipe before issuing new loads ----
    {
      uint32_t a[2][4], bflat[16];
      #pragma unroll
      for (int mi = 0; mi < 2; mi++){
        int r = wm*32 + mi*16 + (lane & 15);
        ldsm4(a[mi], as_u + aBase + (uint32_t)(r*SA2 + ((lane>>4)<<3)) * 2);
      }
      #pragma unroll
      for (int g = 0; g < 4; g++){
        int rr = (lane & 15);
        int c  = wn*64 + g*16 + ((lane>>4)<<3);
        ldsm4t(&bflat[g*4], bs_u + bBase + (uint32_t)(rr*SB2 + c) * 2);
      }
      #pragma unroll
      for (int mi = 0; mi < 2; mi++)
        #pragma unroll
        for (int ni = 0; ni < 8; ni++)
          mma16816(acc[mi][ni], a[mi], &bflat[ni*2]);
    }

    // ---- issue next-stage loads while kk0 MMAs drain ----
    if (ci + 2 < NCHUNK) loadc(ci + 2);
    cp_commit();   // empty group at tail keeps wait<1> honest

    // ---- kk = 1..3 ----
    #pragma unroll
    for (int kk = 1; kk < 4; kk++){
      int k = kk * 16;
      uint32_t a[2][4], bflat[16];
      #pragma unroll
      for (int mi = 0; mi < 2; mi++){
        int r = wm*32 + mi*16 + (lane & 15);
        ldsm4(a[mi], as_u + aBase + (uint32_t)(r*SA2 + k + ((lane>>4)<<3)) * 2);
      }
      #pragma unroll
      for (int g = 0; g < 4; g++){
        int rr = k + (lane & 15);
        int c  = wn*64 + g*16 + ((lane>>4)<<3);
        ldsm4t(&bflat[g*4], bs_u + bBase + (uint32_t)(rr*SB2 + c) * 2);
      }
      #pragma unroll
      for (int mi = 0; mi < 2; mi++)
        #pragma unroll
        for (int ni = 0; ni < 8; ni++)
          mma16816(acc[mi][ni], a[mi], &bflat[ni*2]);
    }
  }
  cp_wait<0>();

  // ---- epilogue: + P + bias, row L2 norm over 128 cols, scaled store ----
  float2 bias2[8];
  #pragma unroll
  for (int ni = 0; ni < 8; ni++){
    int c = wn*64 + ni*8 + (lane&3)*2;
    bias2[ni] = *(const float2*)(bias + c);
  }
  #pragma unroll
  for (int mi = 0; mi < 2; mi++){
    int r0 = m0 + wm*32 + mi*16 + (lane>>2);
    int r1 = r0 + 8;
    float ss0 = 0.f, ss1 = 0.f;
    #pragma unroll
    for (int ni = 0; ni < 8; ni++){
      int c = wn*64 + ni*8 + (lane&3)*2;
      __half2 p0 = *(const __half2*)(gB + (size_t)r0*FDIM + c);
      __half2 p1 = *(const __half2*)(gB + (size_t)r1*FDIM + c);
      float v0 = acc[mi][ni][0] + __low2float(p0)  + bias2[ni].x;
      float v1 = acc[mi][ni][1] + __high2float(p0) + bias2[ni].y;
      float v2 = acc[mi][ni][2] + __low2float(p1)  + bias2[ni].x;
      float v3 = acc[mi][ni][3] + __high2float(p1) + bias2[ni].y;
      acc[mi][ni][0] = v0; acc[mi][ni][1] = v1;
      acc[mi][ni][2] = v2; acc[mi][ni][3] = v3;
      ss0 += v0*v0 + v1*v1;
      ss1 += v2*v2 + v3*v3;
    }
    ss0 += __shfl_xor_sync(0xffffffffu, ss0, 1);
    ss0 += __shfl_xor_sync(0xffffffffu, ss0, 2);
    ss1 += __shfl_xor_sync(0xffffffffu, ss1, 1);
    ss1 += __shfl_xor_sync(0xffffffffu, ss1, 2);
    if ((lane & 3) == 0){
      snorm[wn*BM + (r0 - m0)] = ss0;
      snorm[wn*BM + (r1 - m0)] = ss1;
    }
  }
  __syncthreads();
  #pragma unroll
  for (int mi = 0; mi < 2; mi++){
    int r0 = m0 + wm*32 + mi*16 + (lane>>2);
    int r1 = r0 + 8;
    float t0 = snorm[r0 - m0] + snorm[BM + r0 - m0];
    float t1 = snorm[r1 - m0] + snorm[BM + r1 - m0];
    float inv0 = 1.0f / fmaxf(sqrtf(t0), 1e-12f);
    float inv1 = 1.0f / fmaxf(sqrtf(t1), 1e-12f);
    #pragma unroll
    for (int ni = 0; ni < 8; ni++){
      int c = wn*64 + ni*8 + (lane&3)*2;
      float2 o0 = make_float2(acc[mi][ni][0]*inv0, acc[mi][ni][1]*inv0);
      float2 o1 = make_float2(acc[mi][ni][2]*inv1, acc[mi][ni][3]*inv1);
      *(float2*)(out + ((size_t)b*NROWS + r0)*FDIM + c) = o0;
      *(float2*)(out + ((size_t)b*NROWS + r1)*FDIM + c) = o1;
    }
  }
}

// ---------------- launch ----------------
extern "C" void kernel_launch(void* const* d_in, const int* in_sizes, int n_in,
                              void* d_out, int out_size){
  (void)in_sizes; (void)n_in; (void)out_size;
  const float* x    = (const float*)d_in[0];
  const float* adj  = (const float*)d_in[1];
  const float* w    = (const float*)d_in[2];
  const float* bias = (const float*)d_in[3];
  float* out = (float*)d_out;

  cudaFuncSetAttribute(k_prep, cudaFuncAttributeMaxDynamicSharedMemorySize, K1_SMEM);
  cudaFuncSetAttribute(k_main, cudaFuncAttributeMaxDynamicSharedMemorySize, K2_SMEM);

  k_prep<<<512, 256, K1_SMEM>>>(x, w);
  k_main<<<dim3(BATCH, NROWS/BM), 256, K2_SMEM>>>(adj, bias, out);
}